// round 3
// baseline (speedup 1.0000x reference)
#include <cuda_runtime.h>
#include <cuda_bf16.h>
#include <cstdint>

// S4D Vandermonde kernel.
// out[h, l] = 2 * Re( sum_n Ceff[h,n] * exp(dtA[h,n] * l) ),  l in [0, L)
// Strategy: geometric recurrence in packed fp32x2 (two n-channels per 64-bit
// register), resynced against an accurately-computed start phase every TL
// steps per thread. Thread t of a BT-thread block covers l = base + j*BT + t,
// so the stride ratio is R = exp(dtA * BT) and all stores are coalesced.

#define BT 128   // threads per block
#define TL 32    // l-values per thread (register accumulators)
#define MAXNH 64

typedef unsigned long long u64;

__device__ __forceinline__ u64 pack2(float lo, float hi) {
    u64 d; asm("mov.b64 %0, {%1, %2};" : "=l"(d) : "f"(lo), "f"(hi)); return d;
}
__device__ __forceinline__ float2 unpack2(u64 v) {
    float2 f; asm("mov.b64 {%0, %1}, %2;" : "=f"(f.x), "=f"(f.y) : "l"(v)); return f;
}
__device__ __forceinline__ u64 mul2(u64 a, u64 b) {
    u64 d; asm("mul.rn.f32x2 %0, %1, %2;" : "=l"(d) : "l"(a), "l"(b)); return d;
}
__device__ __forceinline__ u64 add2(u64 a, u64 b) {
    u64 d; asm("add.rn.f32x2 %0, %1, %2;" : "=l"(d) : "l"(a), "l"(b)); return d;
}
__device__ __forceinline__ u64 fma2(u64 a, u64 b, u64 c) {
    u64 d; asm("fma.rn.f32x2 %0, %1, %2, %3;" : "=l"(d) : "l"(a), "l"(b), "l"(c)); return d;
}

__global__ __launch_bounds__(BT)
void s4d_kernel(const float* __restrict__ Cp,
                const float* __restrict__ log_dt,
                const float* __restrict__ log_A_real,
                const float* __restrict__ A_imag,
                float* __restrict__ out,
                int NH, int L)
{
    __shared__ float  sh_dtAre[MAXNH];
    __shared__ double sh_dtAimD[MAXNH];
    __shared__ float  sh_C2re[MAXNH], sh_C2im[MAXNH];
    __shared__ float  sh_Rre[MAXNH],  sh_Rim[MAXNH];

    const int h    = blockIdx.y;
    const int tid  = threadIdx.x;
    const int base = blockIdx.x * (BT * TL);

    // ---- per-(h,n) precompute (replicates reference fp32 rounding path) ----
    if (tid < NH) {
        const int n = tid;
        const float dtv   = expf(log_dt[h]);                 // dt = exp(log_dt), fp32 like ref
        const float Aim   = A_imag[h * NH + n];
        const float eLr   = expf(log_A_real[h * NH + n]);
        const float Are   = -eLr;                            // A = -exp(log_A_real) + i*A_imag
        const float dtAre = Are * dtv;                       // fl(A_re * dt)  (matches ref)
        const float dtAim = Aim * dtv;                       // fl(A_im * dt)  (matches ref)

        // exp(dtA) accurately, then (exp(dtA)-1)/A exactly as the ref does in fp32
        float sn1, cs1; sincosf(dtAim, &sn1, &cs1);          // |dtAim| <= ~10, accurate libcall
        const float mg  = expf(dtAre);
        const float er  = mg * cs1 - 1.0f;
        const float ei  = mg * sn1;
        const float den = Are * Are + Aim * Aim;
        const float inv = 1.0f / den;
        const float qre = (er * Are + ei * Aim) * inv;       // (exp(dtA)-1)/A
        const float qim = (ei * Are - er * Aim) * inv;
        const float Cre = Cp[(h * NH + n) * 2 + 0];
        const float Cim = Cp[(h * NH + n) * 2 + 1];
        sh_C2re[n] = 2.0f * (Cre * qre - Cim * qim);         // fold the final 2x in here
        sh_C2im[n] = 2.0f * (Cre * qim + Cim * qre);

        // Stride ratio R = exp(dtA * BT). dtAim*128 is an exact *2^7 scaling,
        // so accurate sincosf of it gives the true stride phase mod 2pi.
        const float ph = dtAim * (float)BT;
        float sp, cp2; sincosf(ph, &sp, &cp2);
        const float Rm = expf(dtAre * (float)BT);
        sh_Rre[n] = Rm * cp2;
        sh_Rim[n] = Rm * sp;

        sh_dtAre[n]  = dtAre;
        sh_dtAimD[n] = (double)dtAim;
    }
    __syncthreads();

    u64 acc[TL];
    #pragma unroll
    for (int j = 0; j < TL; j++) acc[j] = 0ull;   // packed (0.0f, 0.0f)

    const int    l0  = base + tid;
    const float  l0f = (float)l0;
    const double l0d = (double)l0;
    const int npairs = NH >> 1;

    for (int p = 0; p < npairs; p++) {
        const int nA = 2 * p, nB = 2 * p + 1;

        // ---- accurate chunk-start states: state = Ceff2 * exp(dtA * l0) ----
        float areA, aimA, areB, aimB;
        {
            double th = sh_dtAimD[nA] * l0d;
            double kk = rint(th * 0.15915494309189535);
            float thr = (float)fma(kk, -6.283185307179586, th);   // phase mod 2pi
            float sn, cs; __sincosf(thr, &sn, &cs);
            float m  = __expf(sh_dtAre[nA] * l0f);
            float cr = sh_C2re[nA], ci = sh_C2im[nA];
            areA = m * (cr * cs - ci * sn);
            aimA = m * (cr * sn + ci * cs);
        }
        {
            double th = sh_dtAimD[nB] * l0d;
            double kk = rint(th * 0.15915494309189535);
            float thr = (float)fma(kk, -6.283185307179586, th);
            float sn, cs; __sincosf(thr, &sn, &cs);
            float m  = __expf(sh_dtAre[nB] * l0f);
            float cr = sh_C2re[nB], ci = sh_C2im[nB];
            areB = m * (cr * cs - ci * sn);
            aimB = m * (cr * sn + ci * cs);
        }

        u64 sre2  = pack2(areA, areB);
        u64 sim2  = pack2(aimA, aimB);
        u64 rre2  = pack2(sh_Rre[nA],  sh_Rre[nB]);
        u64 rim2  = pack2(sh_Rim[nA],  sh_Rim[nB]);
        u64 nrim2 = pack2(-sh_Rim[nA], -sh_Rim[nB]);

        // ---- hot loop: 5 packed f32x2 ops per 2 (n,l) elements ----
        #pragma unroll
        for (int j = 0; j < TL; j++) {
            acc[j] = add2(acc[j], sre2);          // accumulate Re halves (both n)
            u64 u = mul2(sre2, rre2);
            u64 v = mul2(sre2, rim2);
            sre2  = fma2(sim2, nrim2, u);         // re' = re*Rre - im*Rim
            sim2  = fma2(sim2, rre2,  v);         // im' = re*Rim + im*Rre
        }
    }

    // ---- coalesced epilogue ----
    float* op = out + (size_t)h * (size_t)L;
    #pragma unroll
    for (int j = 0; j < TL; j++) {
        const int l = base + j * BT + tid;
        if (l < L) {
            float2 f = unpack2(acc[j]);
            op[l] = f.x + f.y;
        }
    }
}

extern "C" void kernel_launch(void* const* d_in, const int* in_sizes, int n_in,
                              void* d_out, int out_size) {
    const float* Cp         = (const float*)d_in[0];  // (H, NH, 2)
    const float* log_dt     = (const float*)d_in[1];  // (H,)
    const float* log_A_real = (const float*)d_in[2];  // (H, NH)
    const float* A_imag     = (const float*)d_in[3];  // (H, NH)
    float* out = (float*)d_out;                       // (H, L)

    const int H  = in_sizes[1];
    const int NH = in_sizes[2] / H;
    const int L  = out_size / H;

    const int chunk = BT * TL;
    dim3 grid((L + chunk - 1) / chunk, H);
    s4d_kernel<<<grid, BT>>>(Cp, log_dt, log_A_real, A_imag, out, NH, L);
}

// round 6
// speedup vs baseline: 1.8323x; 1.8323x over previous
#include <cuda_runtime.h>
#include <cuda_bf16.h>
#include <cstdint>

// S4D Vandermonde kernel.
// out[h, l] = 2 * Re( sum_n Ceff[h,n] * exp(dtA[h,n] * l) ),  l in [0, L)
//
// All-fp32 hot path:
//  - Chunk-start phase via integer fixed-point turns: P = round(frac(dtAim/2pi)*2^32),
//    phase(l) = (int32)(P*l) * 2pi/2^32  -> |err| <= 2^-20 turns. No FP64 in hot path.
//  - Two independent recurrence streams (even/odd j) stepping by R2 = exp(dtA*2*BT)
//    to double ILP on the fma pipe (the serial complex-multiply chain was the limiter).
// Thread t of a BT-thread block covers l = base + j*BT + t (coalesced stores).

#define BT 128   // threads per block
#define TL 32    // l-values per thread (register accumulators)
#define MAXNH 64

typedef unsigned long long u64;

__device__ __forceinline__ u64 pack2(float lo, float hi) {
    u64 d; asm("mov.b64 %0, {%1, %2};" : "=l"(d) : "f"(lo), "f"(hi)); return d;
}
__device__ __forceinline__ float2 unpack2(u64 v) {
    float2 f; asm("mov.b64 {%0, %1}, %2;" : "=f"(f.x), "=f"(f.y) : "l"(v)); return f;
}
__device__ __forceinline__ u64 mul2(u64 a, u64 b) {
    u64 d; asm("mul.rn.f32x2 %0, %1, %2;" : "=l"(d) : "l"(a), "l"(b)); return d;
}
__device__ __forceinline__ u64 add2(u64 a, u64 b) {
    u64 d; asm("add.rn.f32x2 %0, %1, %2;" : "=l"(d) : "l"(a), "l"(b)); return d;
}
__device__ __forceinline__ u64 fma2(u64 a, u64 b, u64 c) {
    u64 d; asm("fma.rn.f32x2 %0, %1, %2, %3;" : "=l"(d) : "l"(a), "l"(b), "l"(c)); return d;
}

__global__ __launch_bounds__(BT)
void s4d_kernel(const float* __restrict__ Cp,
                const float* __restrict__ log_dt,
                const float* __restrict__ log_A_real,
                const float* __restrict__ A_imag,
                float* __restrict__ out,
                int NH, int L)
{
    __shared__ float        sh_dtAre[MAXNH];
    __shared__ unsigned int sh_P[MAXNH];                  // frac(dtAim/2pi) in 2^32 turns
    __shared__ float        sh_C2re[MAXNH], sh_C2im[MAXNH];
    __shared__ float        sh_Rre[MAXNH],  sh_Rim[MAXNH];   // step BT
    __shared__ float        sh_R2re[MAXNH], sh_R2im[MAXNH];  // step 2*BT

    const int h    = blockIdx.y;
    const int tid  = threadIdx.x;
    const int base = blockIdx.x * (BT * TL);

    // ---- per-(h,n) precompute (once per block; FP64 allowed here) ----
    if (tid < NH) {
        const int n = tid;
        const float dtv   = expf(log_dt[h]);                 // dt = exp(log_dt), fp32 like ref
        const float Aim   = A_imag[h * NH + n];
        const float eLr   = expf(log_A_real[h * NH + n]);
        const float Are   = -eLr;                            // A = -exp(log_A_real) + i*A_imag
        const float dtAre = Are * dtv;                       // fl(A_re * dt)  (matches ref)
        const float dtAim = Aim * dtv;                       // fl(A_im * dt)  (matches ref)

        // Ceff2 = 2 * C * (exp(dtA)-1)/A, in fp32 like the reference
        float sn1, cs1; sincosf(dtAim, &sn1, &cs1);
        const float mg  = expf(dtAre);
        const float er  = mg * cs1 - 1.0f;
        const float ei  = mg * sn1;
        const float den = Are * Are + Aim * Aim;
        const float inv = 1.0f / den;
        const float qre = (er * Are + ei * Aim) * inv;
        const float qim = (ei * Are - er * Aim) * inv;
        const float Cre = Cp[(h * NH + n) * 2 + 0];
        const float Cim = Cp[(h * NH + n) * 2 + 1];
        sh_C2re[n] = 2.0f * (Cre * qre - Cim * qim);
        sh_C2im[n] = 2.0f * (Cre * qim + Cim * qre);

        // Integer phase-per-step: P = round(frac(dtAim / 2pi) * 2^32)
        {
            double f  = (double)dtAim * 0.15915494309189535; // dtAim / 2pi
            double fr = f - floor(f);
            sh_P[n] = (unsigned int)(unsigned long long)(fr * 4294967296.0 + 0.5);
        }

        // Stride ratios. dtAim*BT and dtAim*2BT are exact power-of-two scalings of
        // the fp32 dtAim, so accurate sincosf gives the true stride phase mod 2pi.
        {
            float sp, cp2; sincosf(dtAim * (float)BT, &sp, &cp2);
            const float Rm = expf(dtAre * (float)BT);
            sh_Rre[n] = Rm * cp2;  sh_Rim[n] = Rm * sp;
        }
        {
            float sp, cp2; sincosf(dtAim * (float)(2 * BT), &sp, &cp2);
            const float Rm = expf(dtAre * (float)(2 * BT));
            sh_R2re[n] = Rm * cp2;  sh_R2im[n] = Rm * sp;
        }
        sh_dtAre[n] = dtAre;
    }
    __syncthreads();

    u64 acc[TL];
    #pragma unroll
    for (int j = 0; j < TL; j++) acc[j] = 0ull;   // packed (0.0f, 0.0f)

    const unsigned int l0u = (unsigned int)(base + tid);
    const float        l0f = (float)(base + tid);
    const int npairs = NH >> 1;
    const float TWO_PI_OVER_2_32 = 1.4629180792671596e-9f;

    for (int p = 0; p < npairs; p++) {
        const int nA = 2 * p, nB = 2 * p + 1;

        // ---- chunk-start state for stream "even": s = Ceff2 * exp(dtA * l0) ----
        float areA, aimA, areB, aimB;
        {
            float th = (float)(int)(sh_P[nA] * l0u) * TWO_PI_OVER_2_32;  // [-pi, pi)
            float sn, cs; __sincosf(th, &sn, &cs);
            float m  = __expf(sh_dtAre[nA] * l0f);
            float cr = sh_C2re[nA], ci = sh_C2im[nA];
            areA = m * (cr * cs - ci * sn);
            aimA = m * (cr * sn + ci * cs);
        }
        {
            float th = (float)(int)(sh_P[nB] * l0u) * TWO_PI_OVER_2_32;
            float sn, cs; __sincosf(th, &sn, &cs);
            float m  = __expf(sh_dtAre[nB] * l0f);
            float cr = sh_C2re[nB], ci = sh_C2im[nB];
            areB = m * (cr * cs - ci * sn);
            aimB = m * (cr * sn + ci * cs);
        }

        u64 se_re = pack2(areA, areB);
        u64 se_im = pack2(aimA, aimB);

        // stream "odd" = even * R(BT)
        u64 rre  = pack2(sh_Rre[nA],  sh_Rre[nB]);
        u64 rim  = pack2(sh_Rim[nA],  sh_Rim[nB]);
        u64 nrim = pack2(-sh_Rim[nA], -sh_Rim[nB]);
        u64 u0 = mul2(se_re, rre);
        u64 v0 = mul2(se_re, rim);
        u64 so_re = fma2(se_im, nrim, u0);
        u64 so_im = fma2(se_im, rre,  v0);

        // both streams step by R2 = R(2*BT)
        u64 r2re  = pack2(sh_R2re[nA],  sh_R2re[nB]);
        u64 r2im  = pack2(sh_R2im[nA],  sh_R2im[nB]);
        u64 nr2im = pack2(-sh_R2im[nA], -sh_R2im[nB]);

        // ---- hot loop: 10 packed f32x2 ops per 2 j, two independent chains ----
        #pragma unroll
        for (int j = 0; j < TL; j += 2) {
            acc[j] = add2(acc[j], se_re);
            u64 u = mul2(se_re, r2re);
            u64 v = mul2(se_re, r2im);
            se_re = fma2(se_im, nr2im, u);        // re' = re*R2re - im*R2im
            se_im = fma2(se_im, r2re,  v);        // im' = re*R2im + im*R2re

            acc[j + 1] = add2(acc[j + 1], so_re);
            u64 u2 = mul2(so_re, r2re);
            u64 v2 = mul2(so_re, r2im);
            so_re = fma2(so_im, nr2im, u2);
            so_im = fma2(so_im, r2re,  v2);
        }
    }

    // ---- coalesced epilogue ----
    float* op = out + (size_t)h * (size_t)L;
    #pragma unroll
    for (int j = 0; j < TL; j++) {
        const int l = base + j * BT + tid;
        if (l < L) {
            float2 f = unpack2(acc[j]);
            op[l] = f.x + f.y;
        }
    }
}

extern "C" void kernel_launch(void* const* d_in, const int* in_sizes, int n_in,
                              void* d_out, int out_size) {
    const float* Cp         = (const float*)d_in[0];  // (H, NH, 2)
    const float* log_dt     = (const float*)d_in[1];  // (H,)
    const float* log_A_real = (const float*)d_in[2];  // (H, NH)
    const float* A_imag     = (const float*)d_in[3];  // (H, NH)
    float* out = (float*)d_out;                       // (H, L)

    const int H  = in_sizes[1];
    const int NH = in_sizes[2] / H;
    const int L  = out_size / H;

    const int chunk = BT * TL;
    dim3 grid((L + chunk - 1) / chunk, H);
    s4d_kernel<<<grid, BT>>>(Cp, log_dt, log_A_real, A_imag, out, NH, L);
}

// round 8
// speedup vs baseline: 2.4336x; 1.3282x over previous
#include <cuda_runtime.h>
#include <cuda_bf16.h>
#include <cstdint>

// S4D Vandermonde kernel.
// out[h, l] = 2 * Re( sum_n Ceff[h,n] * exp(dtA[h,n] * l) ),  l in [0, L)
//
// R6: real-only Chebyshev-style 2-term recurrence in the hot loop.
//   y_k = Re(s * w^k) satisfies y_{k+1} = t*y_k - d*y_{k-1},
//   t = 2*Re(w), d = |w|^2, w = exp(dtA * 2*BT).
//   -> 3 packed f32x2 ops per (j, n-pair) instead of 5 (full complex mul).
// Chunk-start phase via integer fixed-point turns (no FP64 in hot path):
//   P = round(frac(dtAim/2pi)*2^32), phase(l) = (int32)(P*l)*2pi/2^32.
// Two interleaved streams (even/odd j) for fma-chain ILP.
// Thread t of a BT-thread block covers l = base + j*BT + t (coalesced stores).

#define BT 128   // threads per block
#define TL 32    // l-values per thread (register accumulators)
#define MAXNH 64

typedef unsigned long long u64;

__device__ __forceinline__ u64 pack2(float lo, float hi) {
    u64 d; asm("mov.b64 %0, {%1, %2};" : "=l"(d) : "f"(lo), "f"(hi)); return d;
}
__device__ __forceinline__ float2 unpack2(u64 v) {
    float2 f; asm("mov.b64 {%0, %1}, %2;" : "=f"(f.x), "=f"(f.y) : "l"(v)); return f;
}
__device__ __forceinline__ u64 mul2(u64 a, u64 b) {
    u64 d; asm("mul.rn.f32x2 %0, %1, %2;" : "=l"(d) : "l"(a), "l"(b)); return d;
}
__device__ __forceinline__ u64 add2(u64 a, u64 b) {
    u64 d; asm("add.rn.f32x2 %0, %1, %2;" : "=l"(d) : "l"(a), "l"(b)); return d;
}
__device__ __forceinline__ u64 fma2(u64 a, u64 b, u64 c) {
    u64 d; asm("fma.rn.f32x2 %0, %1, %2, %3;" : "=l"(d) : "l"(a), "l"(b), "l"(c)); return d;
}

__global__ __launch_bounds__(BT)
void s4d_kernel(const float* __restrict__ Cp,
                const float* __restrict__ log_dt,
                const float* __restrict__ log_A_real,
                const float* __restrict__ A_imag,
                float* __restrict__ out,
                int NH, int L)
{
    __shared__ float        sh_dtAre[MAXNH];
    __shared__ unsigned int sh_P[MAXNH];                  // frac(dtAim/2pi) in 2^32 turns
    __shared__ float        sh_C2re[MAXNH], sh_C2im[MAXNH];
    __shared__ float        sh_Rre[MAXNH],  sh_Rim[MAXNH];   // step BT (odd-stream init)
    __shared__ float        sh_R2re[MAXNH], sh_R2im[MAXNH];  // step 2*BT (y1 init)
    __shared__ float        sh_T2[MAXNH],   sh_ND2[MAXNH];   // t = 2*R2re, -d = -|R2|^2

    const int h    = blockIdx.y;
    const int tid  = threadIdx.x;
    const int base = blockIdx.x * (BT * TL);

    // ---- per-(h,n) precompute (once per block; FP64 allowed here) ----
    if (tid < NH) {
        const int n = tid;
        const float dtv   = expf(log_dt[h]);                 // dt = exp(log_dt), fp32 like ref
        const float Aim   = A_imag[h * NH + n];
        const float eLr   = expf(log_A_real[h * NH + n]);
        const float Are   = -eLr;                            // A = -exp(log_A_real) + i*A_imag
        const float dtAre = Are * dtv;                       // fl(A_re * dt)  (matches ref)
        const float dtAim = Aim * dtv;                       // fl(A_im * dt)  (matches ref)

        // Ceff2 = 2 * C * (exp(dtA)-1)/A, in fp32 like the reference
        float sn1, cs1; sincosf(dtAim, &sn1, &cs1);
        const float mg  = expf(dtAre);
        const float er  = mg * cs1 - 1.0f;
        const float ei  = mg * sn1;
        const float den = Are * Are + Aim * Aim;
        const float inv = 1.0f / den;
        const float qre = (er * Are + ei * Aim) * inv;
        const float qim = (ei * Are - er * Aim) * inv;
        const float Cre = Cp[(h * NH + n) * 2 + 0];
        const float Cim = Cp[(h * NH + n) * 2 + 1];
        sh_C2re[n] = 2.0f * (Cre * qre - Cim * qim);
        sh_C2im[n] = 2.0f * (Cre * qim + Cim * qre);

        // Integer phase-per-step: P = round(frac(dtAim / 2pi) * 2^32)
        {
            double f  = (double)dtAim * 0.15915494309189535; // dtAim / 2pi
            double fr = f - floor(f);
            sh_P[n] = (unsigned int)(unsigned long long)(fr * 4294967296.0 + 0.5);
        }

        // Stride ratios. dtAim*BT and dtAim*2BT are exact power-of-two scalings of
        // the fp32 dtAim, so accurate sincosf gives the true stride phase mod 2pi.
        {
            float sp, cp2; sincosf(dtAim * (float)BT, &sp, &cp2);
            const float Rm = expf(dtAre * (float)BT);
            sh_Rre[n] = Rm * cp2;  sh_Rim[n] = Rm * sp;
        }
        {
            float sp, cp2; sincosf(dtAim * (float)(2 * BT), &sp, &cp2);
            const float Rm = expf(dtAre * (float)(2 * BT));
            sh_R2re[n] = Rm * cp2;  sh_R2im[n] = Rm * sp;
            sh_T2[n]   = 2.0f * Rm * cp2;                    // t = 2*Re(R2)
            sh_ND2[n]  = -expf(dtAre * (float)(4 * BT));     // -|R2|^2 = -exp(2*dtAre*2BT)
        }
        sh_dtAre[n] = dtAre;
    }
    __syncthreads();

    u64 acc[TL];
    #pragma unroll
    for (int j = 0; j < TL; j++) acc[j] = 0ull;   // packed (0.0f, 0.0f)

    const unsigned int l0u = (unsigned int)(base + tid);
    const float        l0f = (float)(base + tid);
    const int npairs = NH >> 1;
    const float TWO_PI_OVER_2_32 = 1.4629180792671596e-9f;

    for (int p = 0; p < npairs; p++) {
        const int nA = 2 * p, nB = 2 * p + 1;

        // ---- chunk-start state: s = Ceff2 * exp(dtA * l0) ----
        float areA, aimA, areB, aimB;
        {
            float th = (float)(int)(sh_P[nA] * l0u) * TWO_PI_OVER_2_32;  // [-pi, pi)
            float sn, cs; __sincosf(th, &sn, &cs);
            float m  = __expf(sh_dtAre[nA] * l0f);
            float cr = sh_C2re[nA], ci = sh_C2im[nA];
            areA = m * (cr * cs - ci * sn);
            aimA = m * (cr * sn + ci * cs);
        }
        {
            float th = (float)(int)(sh_P[nB] * l0u) * TWO_PI_OVER_2_32;
            float sn, cs; __sincosf(th, &sn, &cs);
            float m  = __expf(sh_dtAre[nB] * l0f);
            float cr = sh_C2re[nB], ci = sh_C2im[nB];
            areB = m * (cr * cs - ci * sn);
            aimB = m * (cr * sn + ci * cs);
        }

        u64 se_re = pack2(areA, areB);
        u64 se_im = pack2(aimA, aimB);

        // odd stream start: so = se * R(BT)
        u64 rre  = pack2(sh_Rre[nA],   sh_Rre[nB]);
        u64 rim  = pack2(sh_Rim[nA],   sh_Rim[nB]);
        u64 nrim = pack2(-sh_Rim[nA],  -sh_Rim[nB]);
        u64 so_re = fma2(se_im, nrim, mul2(se_re, rre));
        u64 so_im = fma2(se_im, rre,  mul2(se_re, rim));

        // y1 per stream: Re(s * R2)
        u64 r2re  = pack2(sh_R2re[nA],  sh_R2re[nB]);
        u64 nr2im = pack2(-sh_R2im[nA], -sh_R2im[nB]);
        u64 ye0 = se_re;
        u64 ye1 = fma2(se_im, nr2im, mul2(se_re, r2re));
        u64 yo0 = so_re;
        u64 yo1 = fma2(so_im, nr2im, mul2(so_re, r2re));

        // recurrence coefficients (step = 2*BT)
        u64 t2  = pack2(sh_T2[nA],  sh_T2[nB]);
        u64 nd2 = pack2(sh_ND2[nA], sh_ND2[nB]);

        acc[0] = add2(acc[0], ye0);
        acc[1] = add2(acc[1], yo0);
        acc[2] = add2(acc[2], ye1);
        acc[3] = add2(acc[3], yo1);

        // ---- hot loop: y_{k+1} = t*y_k + (-d)*y_{k-1}; 3 packed ops/step/stream ----
        #pragma unroll
        for (int k = 2; k < TL / 2; k++) {
            u64 ye2 = fma2(t2, ye1, mul2(nd2, ye0));
            acc[2 * k] = add2(acc[2 * k], ye2);
            ye0 = ye1; ye1 = ye2;

            u64 yo2 = fma2(t2, yo1, mul2(nd2, yo0));
            acc[2 * k + 1] = add2(acc[2 * k + 1], yo2);
            yo0 = yo1; yo1 = yo2;
        }
    }

    // ---- coalesced epilogue ----
    float* op = out + (size_t)h * (size_t)L;
    #pragma unroll
    for (int j = 0; j < TL; j++) {
        const int l = base + j * BT + tid;
        if (l < L) {
            float2 f = unpack2(acc[j]);
            op[l] = f.x + f.y;
        }
    }
}

extern "C" void kernel_launch(void* const* d_in, const int* in_sizes, int n_in,
                              void* d_out, int out_size) {
    const float* Cp         = (const float*)d_in[0];  // (H, NH, 2)
    const float* log_dt     = (const float*)d_in[1];  // (H,)
    const float* log_A_real = (const float*)d_in[2];  // (H, NH)
    const float* A_imag     = (const float*)d_in[3];  // (H, NH)
    float* out = (float*)d_out;                       // (H, L)

    const int H  = in_sizes[1];
    const int NH = in_sizes[2] / H;
    const int L  = out_size / H;

    const int chunk = BT * TL;
    dim3 grid((L + chunk - 1) / chunk, H);
    s4d_kernel<<<grid, BT>>>(Cp, log_dt, log_A_real, A_imag, out, NH, L);
}